// round 2
// baseline (speedup 1.0000x reference)
#include <cuda_runtime.h>
#include <math.h>

#define N_NODES 10000
#define N_EDGES 160000
#define N_GRAPHS 64
#define FDIM 80
#define TDIM 5
#define F_OUT 16
#define N_LAYERS 4
#define D400 400      // T*F
#define D1600 1600    // T*4F
#define D800000 800000

// ---------------- scratch (device globals; no allocation) ----------------
__device__ float g_H0[D800000];
__device__ float g_H1[D800000];
__device__ float g_A[N_NODES * D400];
__device__ float g_B[N_NODES * D400];
__device__ float g_AGG[N_NODES * D1600];
__device__ float g_TMP[D800000];
__device__ float g_Y[D800000];
__device__ int   g_degi[N_NODES];
__device__ float g_degf[N_NODES];
__device__ int   g_off[N_NODES + 1];
__device__ int   g_cursor[N_NODES];
__device__ int   g_csr[N_EDGES];
__device__ double g_bnsum[FDIM];
__device__ double g_bnsq[FDIM];
__device__ float g_avgld;
__device__ float g_LXC[N_NODES * 40];
__device__ float g_pooled[N_GRAPHS * 40];
__device__ int   g_gcnt[N_GRAPHS];
__device__ int   g_mode;   // 0 = indices are int64, 1 = indices are int32

// branching index reader (mode decided once per run by k_detect)
__device__ __forceinline__ int rd_idx(const void* p, int i) {
    return g_mode ? ((const int*)p)[i] : (int)((const long long*)p)[i];
}

__device__ __forceinline__ float* selH(int par) { return par ? g_H1 : g_H0; }

// ---------------- dtype detection ----------------
__global__ void k_detect(const void* ei) {
    if (threadIdx.x != 0) return;
    const long long* p = (const long long*)ei;
    int mode = 0;
    #pragma unroll
    for (int i = 0; i < 32; i++) {
        long long v = p[i];                 // safe: <=256B of a >=640KB buffer
        if (v < 0 || v >= N_NODES) { mode = 1; break; }
    }
    g_mode = mode;
}

// ---------------- init / degree / csr ----------------
__global__ void k_zero() {
    int i = blockIdx.x * blockDim.x + threadIdx.x;
    if (i < N_NODES) g_degi[i] = 0;
    if (i < N_GRAPHS) g_gcnt[i] = 0;
    if (i < N_GRAPHS * 40) g_pooled[i] = 0.f;
}

__global__ void k_deg(const void* __restrict__ ei) {
    int e = blockIdx.x * blockDim.x + threadIdx.x;
    if (e >= N_EDGES) return;
    int s = rd_idx(ei, e);
    int d = rd_idx(ei, N_EDGES + e);
    if ((unsigned)s >= N_NODES || (unsigned)d >= N_NODES) return;
    atomicAdd(&g_degi[d], 1);
}

__global__ void k_gcnt(const void* __restrict__ batch) {
    int n = blockIdx.x * blockDim.x + threadIdx.x;
    if (n >= N_NODES) return;
    int g = rd_idx(batch, n);
    if ((unsigned)g >= N_GRAPHS) return;
    atomicAdd(&g_gcnt[g], 1);
}

// single-block scan: offsets, cursor, degf, avg_log_deg
__global__ void k_scan() {
    __shared__ int    part[1024];
    __shared__ double dsum[1024];
    int tid = threadIdx.x;
    const int PER = 10;   // 1024*10 >= 10000
    int local[PER];
    int s = 0;
    double ld = 0.0;
    int base = tid * PER;
    #pragma unroll
    for (int i = 0; i < PER; i++) {
        int idx = base + i;
        int v = 0;
        if (idx < N_NODES) {
            v = g_degi[idx];
            ld += log((double)v + 1.0);
        }
        local[i] = v;
        s += v;
    }
    part[tid] = s;
    dsum[tid] = ld;
    __syncthreads();
    for (int ofs = 1; ofs < 1024; ofs <<= 1) {
        int v = 0;
        if (tid >= ofs) v = part[tid - ofs];
        __syncthreads();
        part[tid] += v;
        __syncthreads();
    }
    for (int ofs = 512; ofs > 0; ofs >>= 1) {
        if (tid < ofs) dsum[tid] += dsum[tid + ofs];
        __syncthreads();
    }
    int run = part[tid] - s;   // exclusive prefix
    #pragma unroll
    for (int i = 0; i < PER; i++) {
        int idx = base + i;
        if (idx < N_NODES) {
            g_off[idx] = run;
            g_cursor[idx] = run;
            g_degf[idx] = (float)local[i];
            run += local[i];
        }
    }
    if (tid == 1023) g_off[N_NODES] = part[1023];
    if (tid == 0) g_avgld = (float)(dsum[0] / (double)N_NODES);
}

__global__ void k_scatter(const void* __restrict__ ei) {
    int e = blockIdx.x * blockDim.x + threadIdx.x;
    if (e >= N_EDGES) return;
    int srcv = rd_idx(ei, e);
    int d    = rd_idx(ei, N_EDGES + e);
    if ((unsigned)srcv >= N_NODES || (unsigned)d >= N_NODES) return;
    int pos = atomicAdd(&g_cursor[d], 1);
    if ((unsigned)pos < N_EDGES) g_csr[pos] = srcv;
}

// ---------------- pre-lin ----------------
__global__ void k_prelin(const float* __restrict__ x,
                         const float* __restrict__ W,
                         const float* __restrict__ b) {
    int i = blockIdx.x * blockDim.x + threadIdx.x;
    if (i >= N_NODES * FDIM) return;
    int n = i / FDIM, f = i % FDIM;
    g_H0[i] = x[n * 2] * W[f] + b[f];
}

// ---------------- per-layer GEMM: A = H @ Wtop + preb, B = H @ Wbot ----------------
__global__ void k_gemmAB(int par, const float* __restrict__ preW,
                         const float* __restrict__ preb) {
    const float* H = selH(par);
    int j = blockIdx.x * 32 + threadIdx.x;      // 0..799
    int n = blockIdx.y * 8 + threadIdx.y;       // 0..9999
    if (n >= N_NODES) return;
    const float* h = H + n * FDIM;
    int isA = (j < D400);
    int jj = isA ? j : (j - D400);
    int t = jj / FDIM, o = jj % FDIM;
    const float* w = preW + t * (160 * FDIM) + (isA ? 0 : FDIM) * FDIM + o;
    float acc = 0.f;
    #pragma unroll
    for (int f = 0; f < FDIM; f++) acc += h[f] * w[f * FDIM];
    if (isA) g_A[n * D400 + jj] = acc + preb[jj];
    else     g_B[n * D400 + jj] = acc;
}

// ---------------- edge stats ----------------
__global__ void k_edgestats() {
    int n = blockIdx.x;
    int d = threadIdx.x;
    if (d >= D400) return;
    int beg = g_off[n], end = g_off[n + 1];
    float a = g_A[n * D400 + d];
    float s = 0.f, sq = 0.f;
    float mn = INFINITY, mx = -INFINITY;
    for (int i = beg; i < end; i++) {
        int srcv = g_csr[i];
        float v = a + g_B[srcv * D400 + d];
        s += v; sq += v * v;
        mn = fminf(mn, v); mx = fmaxf(mx, v);
    }
    float dg = g_degf[n];
    float cnt = fmaxf(dg, 1.f);
    float mean = s / cnt;
    float msq = sq / cnt;
    float stdv = sqrtf(fmaxf(msq - mean * mean, 0.f) + 1e-5f);
    if (dg <= 0.f) { mn = 0.f; mx = 0.f; }
    int t = d / FDIM, f = d % FDIM;
    float* g = g_AGG + n * D1600 + t * 320;
    g[f] = mean;
    g[80 + f] = mn;
    g[160 + f] = mx;
    g[240 + f] = stdv;
}

// ---------------- post ----------------
__global__ void k_post(int par, const float* __restrict__ postW,
                       const float* __restrict__ postb) {
    __shared__ float sAgg[4][D1600];
    __shared__ float sXt[4][FDIM];
    const float* H = selH(par);
    int tid = threadIdx.y * 80 + threadIdx.x;   // 0..319
    int nb = blockIdx.x * 4;
    for (int i = tid; i < 4 * D1600; i += 320) {
        int sl = i / D1600, k = i % D1600;
        int nn = nb + sl;
        sAgg[sl][k] = (nn < N_NODES) ? g_AGG[nn * D1600 + k] : 0.f;
    }
    for (int i = tid; i < 4 * FDIM; i += 320) {
        int sl = i / FDIM, k = i % FDIM;
        int nn = nb + sl;
        sXt[sl][k] = (nn < N_NODES) ? H[nn * FDIM + k] : 0.f;
    }
    __syncthreads();
    int slot = threadIdx.y;
    int n = nb + slot;
    if (n >= N_NODES) return;
    int tq = threadIdx.x;
    int t = tq / 16, o = tq % 16;
    const float* W = postW + t * (1040 * 16);
    const float* ag = sAgg[slot] + t * 320;
    const float* xt = sXt[slot];
    float a0 = 0.f, a1 = 0.f, a2 = 0.f, a3 = 0.f;
    const float* w0 = W + o;
    #pragma unroll 4
    for (int f = 0; f < FDIM; f++) a0 += xt[f] * w0[f * 16];
    const float* w1 = W + 80 * 16 + o;
    const float* w2 = W + 400 * 16 + o;
    const float* w3 = W + 720 * 16 + o;
    #pragma unroll 4
    for (int g = 0; g < 320; g++) {
        float v = ag[g];
        a1 += v * w1[g * 16];
        a2 += v * w2[g * 16];
        a3 += v * w3[g * 16];
    }
    float dg = g_degf[n];
    float logd = logf(fmaxf(dg, 1.f) + 1.f);
    float avg = g_avgld;
    float c1 = logd / avg, c2 = avg / logd;
    g_TMP[n * FDIM + tq] = a0 + a1 + c1 * a2 + c2 * a3 + postb[t * 16 + o];
}

// ---------------- lin ----------------
__global__ void k_lin(const float* __restrict__ linW, const float* __restrict__ linb) {
    int i = blockIdx.x * blockDim.x + threadIdx.x;
    if (i >= N_NODES * FDIM) return;
    int n = i / FDIM, o = i % FDIM;
    const float* tr = g_TMP + n * FDIM;
    float acc = linb[o];
    #pragma unroll
    for (int j = 0; j < FDIM; j++) acc += tr[j] * linW[j * FDIM + o];
    g_Y[i] = acc;
}

// ---------------- BN stats ----------------
__global__ void k_bnstats() {
    __shared__ double ss[256], sq[256];
    int o = blockIdx.x;
    double s = 0.0, q = 0.0;
    for (int n = threadIdx.x; n < N_NODES; n += 256) {
        double v = (double)g_Y[n * FDIM + o];
        s += v; q += v * v;
    }
    ss[threadIdx.x] = s; sq[threadIdx.x] = q;
    __syncthreads();
    for (int ofs = 128; ofs > 0; ofs >>= 1) {
        if (threadIdx.x < ofs) { ss[threadIdx.x] += ss[threadIdx.x + ofs]; sq[threadIdx.x] += sq[threadIdx.x + ofs]; }
        __syncthreads();
    }
    if (threadIdx.x == 0) { g_bnsum[o] = ss[0]; g_bnsq[o] = sq[0]; }
}

__global__ void k_bnapply(int par, const float* __restrict__ gamma,
                          const float* __restrict__ beta) {
    float* Hn = selH(par ^ 1);
    int i = blockIdx.x * blockDim.x + threadIdx.x;
    if (i >= N_NODES * FDIM) return;
    int o = i % FDIM;
    double mu = g_bnsum[o] / (double)N_NODES;
    double var = g_bnsq[o] / (double)N_NODES - mu * mu;
    float inv = (float)(1.0 / sqrt(var + 1e-5));
    float y = ((float)(g_Y[i] - (float)mu)) * inv * gamma[o] + beta[o];
    Hn[i] = fmaxf(y, 0.f);
}

// ---------------- readout ----------------
__global__ void k_xc(int par, const float* __restrict__ x) {
    const float* H = selH(par);
    int i = blockIdx.x * blockDim.x + threadIdx.x;
    if (i >= N_NODES * 40) return;
    int n = i / 40, d = i % 40;
    float front = H[n * FDIM + d];
    float behind = H[n * FDIM + 40 + d];
    float assign = x[n * 2 + 1];
    g_LXC[i] = logf(front * assign + behind + 1e-6f);
}

__global__ void k_logscore(const void* __restrict__ batch) {
    int n = blockIdx.x;
    int d = threadIdx.x;
    if (d >= 40) return;
    int beg = g_off[n], end = g_off[n + 1];
    float ls = 0.f;
    for (int i = beg; i < end; i++) {
        int srcv = g_csr[i];
        ls += g_LXC[srcv * 40 + d];
    }
    float val = expf(ls + g_LXC[n * 40 + d]);
    int g = rd_idx(batch, n);
    if ((unsigned)g >= N_GRAPHS) return;
    atomicAdd(&g_pooled[g * 40 + d], val);
}

__global__ void k_final(const float* __restrict__ mlW, const float* __restrict__ mlb,
                        const float* __restrict__ m1W, const float* __restrict__ m1b,
                        const float* __restrict__ m2W, const float* __restrict__ m2b,
                        float* __restrict__ out) {
    int g = threadIdx.x;
    if (g >= N_GRAPHS) return;
    float cnt = fmaxf((float)g_gcnt[g], 1.f);
    float p[40];
    #pragma unroll
    for (int d = 0; d < 40; d++) p[d] = g_pooled[g * 40 + d] / cnt;
    float xl = mlb[0];
    #pragma unroll
    for (int d = 0; d < 40; d++) xl += p[d] * mlW[d];
    float cv = m2b[0];
    for (int j = 0; j < 20; j++) {
        float h = m1b[j];
        #pragma unroll
        for (int d = 0; d < 40; d++) h += p[d] * m1W[d * 20 + j];
        h = 20.f - fmaxf(h, 0.f);
        cv += h * m2W[j];
    }
    out[g] = cv + xl;
}

// ---------------- launch ----------------
extern "C" void kernel_launch(void* const* d_in, const int* in_sizes, int n_in,
                              void* d_out, int out_size) {
    const float* x          = (const float*)d_in[0];
    const void*  ei         = d_in[1];
    const void*  batch      = d_in[2];
    const float* pre_lin_W  = (const float*)d_in[3];
    const float* pre_lin_b  = (const float*)d_in[4];
    const float* pre_W      = (const float*)d_in[5];
    const float* pre_b      = (const float*)d_in[6];
    const float* post_W     = (const float*)d_in[7];
    const float* post_b     = (const float*)d_in[8];
    const float* lin_W      = (const float*)d_in[9];
    const float* lin_b      = (const float*)d_in[10];
    const float* bn_gamma   = (const float*)d_in[11];
    const float* bn_beta    = (const float*)d_in[12];
    const float* mlp_lin_W  = (const float*)d_in[13];
    const float* mlp_lin_b  = (const float*)d_in[14];
    const float* mlp1_W     = (const float*)d_in[15];
    const float* mlp1_b     = (const float*)d_in[16];
    const float* mlp2_W     = (const float*)d_in[17];
    const float* mlp2_b     = (const float*)d_in[18];
    float* out = (float*)d_out;

    k_detect<<<1, 32>>>(ei);
    k_zero<<<(N_NODES + 255) / 256, 256>>>();
    k_deg<<<(N_EDGES + 255) / 256, 256>>>(ei);
    k_gcnt<<<(N_NODES + 255) / 256, 256>>>(batch);
    k_scan<<<1, 1024>>>();
    k_scatter<<<(N_EDGES + 255) / 256, 256>>>(ei);
    k_prelin<<<(N_NODES * FDIM + 255) / 256, 256>>>(x, pre_lin_W, pre_lin_b);

    for (int l = 0; l < N_LAYERS; l++) {
        int par = l & 1;
        const float* preW_l  = pre_W  + l * (TDIM * 160 * FDIM);
        const float* preb_l  = pre_b  + l * (TDIM * FDIM);
        const float* postW_l = post_W + l * (TDIM * 1040 * 16);
        const float* postb_l = post_b + l * (TDIM * 16);
        const float* linW_l  = lin_W  + l * (FDIM * FDIM);
        const float* linb_l  = lin_b  + l * FDIM;
        const float* gam_l   = bn_gamma + l * FDIM;
        const float* bet_l   = bn_beta  + l * FDIM;

        dim3 gb(25, 1250), tb(32, 8);
        k_gemmAB<<<gb, tb>>>(par, preW_l, preb_l);
        k_edgestats<<<N_NODES, 416>>>();
        dim3 tp(80, 4);
        k_post<<<(N_NODES + 3) / 4, tp>>>(par, postW_l, postb_l);
        k_lin<<<(N_NODES * FDIM + 255) / 256, 256>>>(linW_l, linb_l);
        k_bnstats<<<FDIM, 256>>>();
        k_bnapply<<<(N_NODES * FDIM + 255) / 256, 256>>>(par, gam_l, bet_l);
    }

    k_xc<<<(N_NODES * 40 + 255) / 256, 256>>>(0, x);
    k_logscore<<<N_NODES, 64>>>(batch);
    k_final<<<1, 64>>>(mlp_lin_W, mlp_lin_b, mlp1_W, mlp1_b, mlp2_W, mlp2_b, out);
}

// round 3
// speedup vs baseline: 2.0592x; 2.0592x over previous
#include <cuda_runtime.h>
#include <math.h>

#define N_NODES 10000
#define N_EDGES 160000
#define N_GRAPHS 64
#define FDIM 80
#define TDIM 5
#define F_OUT 16
#define N_LAYERS 4
#define D400 400      // T*F
#define D1600 1600    // T*4F
#define D800000 800000

// ---------------- scratch (device globals; no allocation) ----------------
__device__ float g_H0[D800000];
__device__ float g_H1[D800000];
__device__ float g_A[N_NODES * D400];
__device__ float g_B[N_NODES * D400];
__device__ float g_AGG[N_NODES * D1600];
__device__ float g_TMP[D800000];
__device__ float g_Y[D800000];
__device__ float g_Wpk[FDIM * 800];
__device__ int   g_degi[N_NODES];
__device__ float g_degf[N_NODES];
__device__ float g_c1[N_NODES];
__device__ float g_c2[N_NODES];
__device__ int   g_off[N_NODES + 1];
__device__ int   g_cursor[N_NODES];
__device__ int   g_csr[N_EDGES];
__device__ double g_bnsum[FDIM];
__device__ double g_bnsq[FDIM];
__device__ float g_avgld;
__device__ float g_LXC[N_NODES * 40];
__device__ float g_pooled[N_GRAPHS * 40];
__device__ int   g_gcnt[N_GRAPHS];
__device__ int   g_mode;   // 0 = indices are int64, 1 = indices are int32

__device__ __forceinline__ int rd_idx(const void* p, int i) {
    return g_mode ? ((const int*)p)[i] : (int)((const long long*)p)[i];
}
__device__ __forceinline__ float* selH(int par) { return par ? g_H1 : g_H0; }

// ---------------- dtype detection ----------------
__global__ void k_detect(const void* ei) {
    if (threadIdx.x != 0) return;
    const long long* p = (const long long*)ei;
    int mode = 0;
    #pragma unroll
    for (int i = 0; i < 32; i++) {
        long long v = p[i];
        if (v < 0 || v >= N_NODES) { mode = 1; break; }
    }
    g_mode = mode;
}

// ---------------- init / degree / csr ----------------
__global__ void k_zero() {
    int i = blockIdx.x * blockDim.x + threadIdx.x;
    if (i < N_NODES) g_degi[i] = 0;
    if (i < N_GRAPHS) g_gcnt[i] = 0;
    if (i < N_GRAPHS * 40) g_pooled[i] = 0.f;
}

__global__ void k_deg(const void* __restrict__ ei) {
    int e = blockIdx.x * blockDim.x + threadIdx.x;
    if (e >= N_EDGES) return;
    int s = rd_idx(ei, e);
    int d = rd_idx(ei, N_EDGES + e);
    if ((unsigned)s >= N_NODES || (unsigned)d >= N_NODES) return;
    atomicAdd(&g_degi[d], 1);
}

__global__ void k_gcnt(const void* __restrict__ batch) {
    int n = blockIdx.x * blockDim.x + threadIdx.x;
    if (n >= N_NODES) return;
    int g = rd_idx(batch, n);
    if ((unsigned)g >= N_GRAPHS) return;
    atomicAdd(&g_gcnt[g], 1);
}

__global__ void k_scan() {
    __shared__ int    part[1024];
    __shared__ double dsum[1024];
    int tid = threadIdx.x;
    const int PER = 10;
    int local[PER];
    int s = 0;
    double ld = 0.0;
    int base = tid * PER;
    #pragma unroll
    for (int i = 0; i < PER; i++) {
        int idx = base + i;
        int v = 0;
        if (idx < N_NODES) {
            v = g_degi[idx];
            ld += log((double)v + 1.0);
        }
        local[i] = v;
        s += v;
    }
    part[tid] = s;
    dsum[tid] = ld;
    __syncthreads();
    for (int ofs = 1; ofs < 1024; ofs <<= 1) {
        int v = 0;
        if (tid >= ofs) v = part[tid - ofs];
        __syncthreads();
        part[tid] += v;
        __syncthreads();
    }
    for (int ofs = 512; ofs > 0; ofs >>= 1) {
        if (tid < ofs) dsum[tid] += dsum[tid + ofs];
        __syncthreads();
    }
    int run = part[tid] - s;
    #pragma unroll
    for (int i = 0; i < PER; i++) {
        int idx = base + i;
        if (idx < N_NODES) {
            g_off[idx] = run;
            g_cursor[idx] = run;
            g_degf[idx] = (float)local[i];
            run += local[i];
        }
    }
    if (tid == 1023) g_off[N_NODES] = part[1023];
    if (tid == 0) g_avgld = (float)(dsum[0] / (double)N_NODES);
}

__global__ void k_coef() {
    int n = blockIdx.x * blockDim.x + threadIdx.x;
    if (n >= N_NODES) return;
    float logd = logf(fmaxf(g_degf[n], 1.f) + 1.f);
    float avg = g_avgld;
    g_c1[n] = logd / avg;
    g_c2[n] = avg / logd;
}

__global__ void k_scatter(const void* __restrict__ ei) {
    int e = blockIdx.x * blockDim.x + threadIdx.x;
    if (e >= N_EDGES) return;
    int srcv = rd_idx(ei, e);
    int d    = rd_idx(ei, N_EDGES + e);
    if ((unsigned)srcv >= N_NODES || (unsigned)d >= N_NODES) return;
    int pos = atomicAdd(&g_cursor[d], 1);
    if ((unsigned)pos < N_EDGES) g_csr[pos] = srcv;
}

// ---------------- pre-lin ----------------
__global__ void k_prelin(const float* __restrict__ x,
                         const float* __restrict__ W,
                         const float* __restrict__ b) {
    int i = blockIdx.x * blockDim.x + threadIdx.x;
    if (i >= N_NODES * FDIM) return;
    int n = i / FDIM, f = i % FDIM;
    g_H0[i] = x[n * 2] * W[f] + b[f];
}

// ---------------- weight repack: Wpk[f][j], j<400 -> Wtop, else Wbot ----------------
__global__ void k_repack(const float* __restrict__ preW) {
    int i = blockIdx.x * blockDim.x + threadIdx.x;
    if (i >= FDIM * 800) return;
    int f = i / 800, j = i % 800;
    int isA = (j < 400);
    int jj = isA ? j : j - 400;
    int t = jj / FDIM, o = jj % FDIM;
    g_Wpk[i] = preW[t * 160 * FDIM + (isA ? f : FDIM + f) * FDIM + o];
}

// ---------------- tiled GEMM: C[10000, N] = Ain[10000, 80] @ Bw[80, N] ----------------
// mode 0: split write to g_A (+bias) / g_B.  mode 1: g_Y = C + bias.
__global__ void k_gemm(const float* __restrict__ Ain, const float* __restrict__ Bw,
                       int N, int mode, const float* __restrict__ bias) {
    __shared__ float sH[16][68];
    __shared__ float sW[16][64];
    int bm = blockIdx.y * 64, bn = blockIdx.x * 64;
    int tid = threadIdx.x;
    int tx = tid & 15, ty = tid >> 4;
    float acc[4][4];
    #pragma unroll
    for (int i = 0; i < 4; i++)
        #pragma unroll
        for (int j = 0; j < 4; j++) acc[i][j] = 0.f;

    #pragma unroll
    for (int kt = 0; kt < 5; kt++) {
        {   // load A tile (64 rows x 16 k), store transposed
            int row = tid >> 2;
            int c4  = (tid & 3) * 4;
            int m = bm + row;
            float4 v = make_float4(0.f, 0.f, 0.f, 0.f);
            if (m < N_NODES) v = *(const float4*)&Ain[m * FDIM + kt * 16 + c4];
            sH[c4][row] = v.x; sH[c4 + 1][row] = v.y;
            sH[c4 + 2][row] = v.z; sH[c4 + 3][row] = v.w;
        }
        {   // load W tile (16 k x 64 n)
            int krow = tid >> 4;
            int c4 = (tid & 15) * 4;
            int j = bn + c4;
            float4 v = make_float4(0.f, 0.f, 0.f, 0.f);
            if (j < N) v = *(const float4*)&Bw[(kt * 16 + krow) * N + j];
            *(float4*)&sW[krow][c4] = v;
        }
        __syncthreads();
        #pragma unroll
        for (int k = 0; k < 16; k++) {
            float4 a = *(float4*)&sH[k][ty * 4];
            float4 b = *(float4*)&sW[k][tx * 4];
            float av[4] = {a.x, a.y, a.z, a.w};
            float bv[4] = {b.x, b.y, b.z, b.w};
            #pragma unroll
            for (int i = 0; i < 4; i++)
                #pragma unroll
                for (int j = 0; j < 4; j++) acc[i][j] += av[i] * bv[j];
        }
        __syncthreads();
    }
    #pragma unroll
    for (int i = 0; i < 4; i++) {
        int m = bm + ty * 4 + i;
        if (m >= N_NODES) continue;
        #pragma unroll
        for (int j = 0; j < 4; j++) {
            int col = bn + tx * 4 + j;
            if (col >= N) continue;
            float c = acc[i][j];
            if (mode == 0) {
                if (col < 400) g_A[m * 400 + col] = c + bias[col];
                else           g_B[m * 400 + col - 400] = c;
            } else {
                g_Y[m * FDIM + col] = c + bias[col];
            }
        }
    }
}

// ---------------- edge stats ----------------
__global__ void k_edgestats() {
    int n = blockIdx.x;
    int d = threadIdx.x;
    if (d >= D400) return;
    int beg = g_off[n], end = g_off[n + 1];
    float a = g_A[n * D400 + d];
    float s = 0.f, sq = 0.f;
    float mn = INFINITY, mx = -INFINITY;
    for (int i = beg; i < end; i++) {
        int srcv = g_csr[i];
        float v = a + g_B[srcv * D400 + d];
        s += v; sq += v * v;
        mn = fminf(mn, v); mx = fmaxf(mx, v);
    }
    float dg = g_degf[n];
    float cnt = fmaxf(dg, 1.f);
    float mean = s / cnt;
    float msq = sq / cnt;
    float stdv = sqrtf(fmaxf(msq - mean * mean, 0.f) + 1e-5f);
    if (dg <= 0.f) { mn = 0.f; mx = 0.f; }
    int t = d / FDIM, f = d % FDIM;
    float* g = g_AGG + n * D1600 + t * 320;
    g[f] = mean;
    g[80 + f] = mn;
    g[160 + f] = mx;
    g[240 + f] = stdv;
}

// ---------------- post (register-tiled): out[n, t*16+o] ----------------
__global__ void k_post2(int par, const float* __restrict__ postW,
                        const float* __restrict__ postb) {
    __shared__ float sA[32][128];        // [k][n]
    __shared__ float sW[3][32][16];
    __shared__ float sW0[16][16];
    const float* H = selH(par);
    int t  = blockIdx.y;
    int n0 = blockIdx.x * 128;
    int tid = threadIdx.x;               // 256
    int o  = tid & 15;
    int ny = tid >> 4;                   // 0..15 (8 nodes each)
    const float* W = postW + t * (1040 * 16);

    float a0[8], a1[8], a2[8], a3[8];
    #pragma unroll
    for (int i = 0; i < 8; i++) { a0[i] = a1[i] = a2[i] = a3[i] = 0.f; }

    // ---- agg segments: K = 320, tiles of 32 ----
    for (int kt = 0; kt < 10; kt++) {
        #pragma unroll
        for (int it = 0; it < 4; it++) {
            int f4 = tid + it * 256;          // 0..1023
            int n  = f4 >> 3;
            int kq = (f4 & 7) * 4;
            int nn = n0 + n;
            float4 v = make_float4(0.f, 0.f, 0.f, 0.f);
            if (nn < N_NODES)
                v = *(const float4*)&g_AGG[nn * 1600 + t * 320 + kt * 32 + kq];
            sA[kq][n] = v.x; sA[kq + 1][n] = v.y;
            sA[kq + 2][n] = v.z; sA[kq + 3][n] = v.w;
        }
        #pragma unroll
        for (int it = 0; it < 2; it++) {
            int idx = tid + it * 256;         // 0..511
            int k = idx >> 4, oo = idx & 15;
            int kg = kt * 32 + k;
            sW[0][k][oo] = W[(80  + kg) * 16 + oo];
            sW[1][k][oo] = W[(400 + kg) * 16 + oo];
            sW[2][k][oo] = W[(720 + kg) * 16 + oo];
        }
        __syncthreads();
        #pragma unroll
        for (int k = 0; k < 32; k++) {
            float w1 = sW[0][k][o], w2 = sW[1][k][o], w3 = sW[2][k][o];
            float4 va = *(float4*)&sA[k][ny * 8];
            float4 vb = *(float4*)&sA[k][ny * 8 + 4];
            float av[8] = {va.x, va.y, va.z, va.w, vb.x, vb.y, vb.z, vb.w};
            #pragma unroll
            for (int i = 0; i < 8; i++) {
                a1[i] += av[i] * w1;
                a2[i] += av[i] * w2;
                a3[i] += av[i] * w3;
            }
        }
        __syncthreads();
    }

    // ---- xt segment: K = 80, tiles of 16 ----
    for (int kt = 0; kt < 5; kt++) {
        #pragma unroll
        for (int it = 0; it < 2; it++) {
            int f4 = tid + it * 256;          // 0..511
            int n  = f4 >> 2;
            int kq = (f4 & 3) * 4;
            int nn = n0 + n;
            float4 v = make_float4(0.f, 0.f, 0.f, 0.f);
            if (nn < N_NODES)
                v = *(const float4*)&H[nn * FDIM + kt * 16 + kq];
            sA[kq][n] = v.x; sA[kq + 1][n] = v.y;
            sA[kq + 2][n] = v.z; sA[kq + 3][n] = v.w;
        }
        {
            int k = tid >> 4, oo = tid & 15;
            sW0[k][oo] = W[(kt * 16 + k) * 16 + oo];
        }
        __syncthreads();
        #pragma unroll
        for (int k = 0; k < 16; k++) {
            float w0 = sW0[k][o];
            float4 va = *(float4*)&sA[k][ny * 8];
            float4 vb = *(float4*)&sA[k][ny * 8 + 4];
            float av[8] = {va.x, va.y, va.z, va.w, vb.x, vb.y, vb.z, vb.w};
            #pragma unroll
            for (int i = 0; i < 8; i++) a0[i] += av[i] * w0;
        }
        __syncthreads();
    }

    float bb = postb[t * 16 + o];
    #pragma unroll
    for (int i = 0; i < 8; i++) {
        int nn = n0 + ny * 8 + i;
        if (nn < N_NODES) {
            float c1 = g_c1[nn], c2 = g_c2[nn];
            g_TMP[nn * FDIM + t * 16 + o] = a0[i] + a1[i] + c1 * a2[i] + c2 * a3[i] + bb;
        }
    }
}

// ---------------- BN stats ----------------
__global__ void k_bnstats() {
    __shared__ double ss[256], sq[256];
    int o = blockIdx.x;
    double s = 0.0, q = 0.0;
    for (int n = threadIdx.x; n < N_NODES; n += 256) {
        double v = (double)g_Y[n * FDIM + o];
        s += v; q += v * v;
    }
    ss[threadIdx.x] = s; sq[threadIdx.x] = q;
    __syncthreads();
    for (int ofs = 128; ofs > 0; ofs >>= 1) {
        if (threadIdx.x < ofs) { ss[threadIdx.x] += ss[threadIdx.x + ofs]; sq[threadIdx.x] += sq[threadIdx.x + ofs]; }
        __syncthreads();
    }
    if (threadIdx.x == 0) { g_bnsum[o] = ss[0]; g_bnsq[o] = sq[0]; }
}

__global__ void k_bnapply(int par, const float* __restrict__ gamma,
                          const float* __restrict__ beta) {
    float* Hn = selH(par ^ 1);
    int i = blockIdx.x * blockDim.x + threadIdx.x;
    if (i >= N_NODES * FDIM) return;
    int o = i % FDIM;
    double mu = g_bnsum[o] / (double)N_NODES;
    double var = g_bnsq[o] / (double)N_NODES - mu * mu;
    float inv = (float)(1.0 / sqrt(var + 1e-5));
    float y = ((float)(g_Y[i] - (float)mu)) * inv * gamma[o] + beta[o];
    Hn[i] = fmaxf(y, 0.f);
}

// ---------------- readout ----------------
__global__ void k_xc(int par, const float* __restrict__ x) {
    const float* H = selH(par);
    int i = blockIdx.x * blockDim.x + threadIdx.x;
    if (i >= N_NODES * 40) return;
    int n = i / 40, d = i % 40;
    float front = H[n * FDIM + d];
    float behind = H[n * FDIM + 40 + d];
    float assign = x[n * 2 + 1];
    g_LXC[i] = logf(front * assign + behind + 1e-6f);
}

__global__ void k_logscore(const void* __restrict__ batch) {
    int n = blockIdx.x;
    int d = threadIdx.x;
    if (d >= 40) return;
    int beg = g_off[n], end = g_off[n + 1];
    float ls = 0.f;
    for (int i = beg; i < end; i++) {
        int srcv = g_csr[i];
        ls += g_LXC[srcv * 40 + d];
    }
    float val = expf(ls + g_LXC[n * 40 + d]);
    int g = rd_idx(batch, n);
    if ((unsigned)g >= N_GRAPHS) return;
    atomicAdd(&g_pooled[g * 40 + d], val);
}

__global__ void k_final(const float* __restrict__ mlW, const float* __restrict__ mlb,
                        const float* __restrict__ m1W, const float* __restrict__ m1b,
                        const float* __restrict__ m2W, const float* __restrict__ m2b,
                        float* __restrict__ out) {
    int g = threadIdx.x;
    if (g >= N_GRAPHS) return;
    float cnt = fmaxf((float)g_gcnt[g], 1.f);
    float p[40];
    #pragma unroll
    for (int d = 0; d < 40; d++) p[d] = g_pooled[g * 40 + d] / cnt;
    float xl = mlb[0];
    #pragma unroll
    for (int d = 0; d < 40; d++) xl += p[d] * mlW[d];
    float cv = m2b[0];
    for (int j = 0; j < 20; j++) {
        float h = m1b[j];
        #pragma unroll
        for (int d = 0; d < 40; d++) h += p[d] * m1W[d * 20 + j];
        h = 20.f - fmaxf(h, 0.f);
        cv += h * m2W[j];
    }
    out[g] = cv + xl;
}

// ---------------- launch ----------------
extern "C" void kernel_launch(void* const* d_in, const int* in_sizes, int n_in,
                              void* d_out, int out_size) {
    const float* x          = (const float*)d_in[0];
    const void*  ei         = d_in[1];
    const void*  batch      = d_in[2];
    const float* pre_lin_W  = (const float*)d_in[3];
    const float* pre_lin_b  = (const float*)d_in[4];
    const float* pre_W      = (const float*)d_in[5];
    const float* pre_b      = (const float*)d_in[6];
    const float* post_W     = (const float*)d_in[7];
    const float* post_b     = (const float*)d_in[8];
    const float* lin_W      = (const float*)d_in[9];
    const float* lin_b      = (const float*)d_in[10];
    const float* bn_gamma   = (const float*)d_in[11];
    const float* bn_beta    = (const float*)d_in[12];
    const float* mlp_lin_W  = (const float*)d_in[13];
    const float* mlp_lin_b  = (const float*)d_in[14];
    const float* mlp1_W     = (const float*)d_in[15];
    const float* mlp1_b     = (const float*)d_in[16];
    const float* mlp2_W     = (const float*)d_in[17];
    const float* mlp2_b     = (const float*)d_in[18];
    float* out = (float*)d_out;

    k_detect<<<1, 32>>>(ei);
    k_zero<<<(N_NODES + 255) / 256, 256>>>();
    k_deg<<<(N_EDGES + 255) / 256, 256>>>(ei);
    k_gcnt<<<(N_NODES + 255) / 256, 256>>>(batch);
    k_scan<<<1, 1024>>>();
    k_coef<<<(N_NODES + 255) / 256, 256>>>();
    k_scatter<<<(N_EDGES + 255) / 256, 256>>>(ei);
    k_prelin<<<(N_NODES * FDIM + 255) / 256, 256>>>(x, pre_lin_W, pre_lin_b);

    for (int l = 0; l < N_LAYERS; l++) {
        int par = l & 1;
        const float* preW_l  = pre_W  + l * (TDIM * 160 * FDIM);
        const float* preb_l  = pre_b  + l * (TDIM * FDIM);
        const float* postW_l = post_W + l * (TDIM * 1040 * 16);
        const float* postb_l = post_b + l * (TDIM * 16);
        const float* linW_l  = lin_W  + l * (FDIM * FDIM);
        const float* linb_l  = lin_b  + l * FDIM;
        const float* gam_l   = bn_gamma + l * FDIM;
        const float* bet_l   = bn_beta  + l * FDIM;

        k_repack<<<(FDIM * 800 + 255) / 256, 256>>>(preW_l);

        // A|B = H @ Wpk  (N=800)
        {
            float* dummy = nullptr;
            (void)dummy;
            const float* Hin = par ? g_H1 : g_H0;
            // device-symbol pointers: pass via kernel that selects internally is
            // not possible for Ain; use cudaGetSymbolAddress-free trick: selH is
            // device-side; instead pass par through a tiny wrapper kernel — but
            // k_gemm takes a raw pointer. Use address-of device globals on host:
            // cudaGetSymbolAddress is allowed (no allocation). We instead launch
            // with pointers obtained below.
        }
        {
            void* hptr0; void* hptr1; void* wpk; void* tmp;
            cudaGetSymbolAddress(&hptr0, g_H0);
            cudaGetSymbolAddress(&hptr1, g_H1);
            cudaGetSymbolAddress(&wpk, g_Wpk);
            cudaGetSymbolAddress(&tmp, g_TMP);
            const float* Hin = (const float*)(par ? hptr1 : hptr0);
            dim3 gab((800 + 63) / 64, (N_NODES + 63) / 64);
            k_gemm<<<gab, 256>>>(Hin, (const float*)wpk, 800, 0, preb_l);

            k_edgestats<<<N_NODES, 416>>>();

            dim3 gp((N_NODES + 127) / 128, TDIM);
            k_post2<<<gp, 256>>>(par, postW_l, postb_l);

            dim3 gl((FDIM + 63) / 64, (N_NODES + 63) / 64);
            k_gemm<<<gl, 256>>>((const float*)tmp, linW_l, FDIM, 1, linb_l);
        }

        k_bnstats<<<FDIM, 256>>>();
        k_bnapply<<<(N_NODES * FDIM + 255) / 256, 256>>>(par, gam_l, bet_l);
    }

    k_xc<<<(N_NODES * 40 + 255) / 256, 256>>>(0, x);
    k_logscore<<<N_NODES, 64>>>(batch);
    k_final<<<1, 64>>>(mlp_lin_W, mlp_lin_b, mlp1_W, mlp1_b, mlp2_W, mlp2_b, out);
}